// round 12
// baseline (speedup 1.0000x reference)
#include <cuda_runtime.h>
#include <math.h>
#include <stdint.h>

#define DIM   384
#define HID   1536
#define BATCH 4
#define SEQ   2048
#define NTOK  (BATCH*SEQ)   /* 8192 tokens */
#define HEADS 6
#define DH    64

// ---------------- scratch (device globals; no allocation allowed) ----------
__device__ float g_ln  [NTOK * DIM];
__device__ float g_qkv [NTOK * 3 * DIM];
__device__ float g_attn[NTOK * DIM];
__device__ float g_x1  [NTOK * DIM];
__device__ float g_h   [NTOK * HID];

// ---------------- helpers ---------------------------------------------------
__device__ __forceinline__ void mma_tf32(float c[4], const uint32_t a[4], const uint32_t b[2]) {
    asm volatile(
        "mma.sync.aligned.m16n8k8.row.col.f32.tf32.tf32.f32 "
        "{%0,%1,%2,%3}, {%4,%5,%6,%7}, {%8,%9}, {%0,%1,%2,%3};"
        : "+f"(c[0]), "+f"(c[1]), "+f"(c[2]), "+f"(c[3])
        : "r"(a[0]), "r"(a[1]), "r"(a[2]), "r"(a[3]), "r"(b[0]), "r"(b[1]));
}
__device__ __forceinline__ uint32_t cvta_s(const void* p) {
    return (uint32_t)__cvta_generic_to_shared(p);
}
__device__ __forceinline__ void cpa16(uint32_t dst, const void* src) {
    asm volatile("cp.async.cg.shared.global [%0], [%1], 16;" :: "r"(dst), "l"(src));
}
__device__ __forceinline__ void cp_commit() { asm volatile("cp.async.commit_group;"); }
__device__ __forceinline__ void cp_wait1()  { asm volatile("cp.async.wait_group 1;"); }
__device__ __forceinline__ void cp_wait0()  { asm volatile("cp.async.wait_group 0;"); }

// ---------------- LayerNorm: one warp per 384-elem row ---------------------
__global__ __launch_bounds__(256) void ln_kernel(
    const float* __restrict__ x, const float* __restrict__ g,
    const float* __restrict__ b, float* __restrict__ out)
{
    int warp = (blockIdx.x * blockDim.x + threadIdx.x) >> 5;
    int lane = threadIdx.x & 31;
    if (warp >= NTOK) return;
    const float* xr = x + (size_t)warp * DIM;

    float v[12];
    float s = 0.f;
#pragma unroll
    for (int i = 0; i < 12; i++) { v[i] = xr[lane + i * 32]; s += v[i]; }
#pragma unroll
    for (int o = 16; o > 0; o >>= 1) s += __shfl_xor_sync(0xffffffffu, s, o);
    float mu = s * (1.0f / DIM);
    float vs = 0.f;
#pragma unroll
    for (int i = 0; i < 12; i++) { float d = v[i] - mu; vs += d * d; }
#pragma unroll
    for (int o = 16; o > 0; o >>= 1) vs += __shfl_xor_sync(0xffffffffu, vs, o);
    float rstd = rsqrtf(vs * (1.0f / DIM) + 1e-6f);

    float* orow = out + (size_t)warp * DIM;
#pragma unroll
    for (int i = 0; i < 12; i++) {
        int c = lane + i * 32;
        orow[c] = (v[i] - mu) * rstd * g[c] + b[c];
    }
}

// ---------------- tf32 GEMM: 128x64 tile, 3-stage cp.async ------------------
// A [M][K] row-major, W [K][N] row-major. Per stage: As[128][36] + Bs[32][72].
// 256 threads = 8 warps (4 wm x 2 wn), warp tile 32x32 (mf2 x nf4).
#define ASTG   (128 * 36)
#define BSTG   (32 * 72)
#define STGF   (ASTG + BSTG)
#define GEMM_SMEM (3 * STGF * 4)   /* 82944 bytes */

template <int EPI>
__global__ __launch_bounds__(256, 2) void gemm_tc(
    const float* __restrict__ A, const float* __restrict__ W,
    const float* __restrict__ bias, const float* __restrict__ res,
    float* __restrict__ C, int M, int K, int N)
{
    extern __shared__ float smem[];

    const int tid  = threadIdx.x;
    const int lane = tid & 31;
    const int wid  = tid >> 5;
    const int wm   = wid & 3;          // 0..3 (m-warps)
    const int wn   = wid >> 2;         // 0..1 (n-warps)
    const int bm   = blockIdx.y * 128;
    const int bn   = blockIdx.x * 64;

    const int a_kq = (tid & 7) << 2;   // A fill: k-quad
    const int a_mr = tid >> 3;         // A fill: row (x4 -> 128)
    const int b_r  = tid >> 3;         // B fill: k-row 0..31
    const int b_q  = tid & 7;          // B fill: quad (and +8)
    const int fr   = lane >> 2;
    const int fc   = lane & 3;

    float acc[2][4][4];
#pragma unroll
    for (int mf = 0; mf < 2; mf++)
#pragma unroll
        for (int nf = 0; nf < 4; nf++)
#pragma unroll
            for (int i = 0; i < 4; i++) acc[mf][nf][i] = 0.f;

    const int NK = K >> 5;

    auto issue = [&](int kb) {
        float* dst = smem + (kb % 3) * STGF;
        const int k0 = kb << 5;
#pragma unroll
        for (int mi = 0; mi < 4; mi++) {
            int m = mi * 32 + a_mr;
            cpa16(cvta_s(dst + m * 36 + a_kq), &A[(size_t)(bm + m) * K + k0 + a_kq]);
        }
        cpa16(cvta_s(dst + ASTG + b_r * 72 + b_q * 4),
              &W[(size_t)(k0 + b_r) * N + bn + b_q * 4]);
        cpa16(cvta_s(dst + ASTG + b_r * 72 + (b_q + 8) * 4),
              &W[(size_t)(k0 + b_r) * N + bn + (b_q + 8) * 4]);
        cp_commit();
    };

    issue(0);
    if (NK > 1) issue(1);

    for (int kb = 0; kb < NK; kb++) {
        if (kb + 1 < NK) cp_wait1(); else cp_wait0();
        __syncthreads();
        if (kb + 2 < NK) issue(kb + 2);

        const float* As = smem + (kb % 3) * STGF;
        const float* Bs = As + ASTG;

#pragma unroll
        for (int ks = 0; ks < 4; ks++) {
            const int kb8 = ks * 8;
            uint32_t afr[2][4], bfr[4][2];
#pragma unroll
            for (int mf = 0; mf < 2; mf++) {
                int r = wm * 32 + mf * 16 + fr;
                int c = kb8 + fc;
                afr[mf][0] = __float_as_uint(As[r * 36 + c]);
                afr[mf][1] = __float_as_uint(As[(r + 8) * 36 + c]);
                afr[mf][2] = __float_as_uint(As[r * 36 + c + 4]);
                afr[mf][3] = __float_as_uint(As[(r + 8) * 36 + c + 4]);
            }
#pragma unroll
            for (int nf = 0; nf < 4; nf++) {
                int n = wn * 32 + nf * 8 + fr;
                bfr[nf][0] = __float_as_uint(Bs[(kb8 + fc) * 72 + n]);
                bfr[nf][1] = __float_as_uint(Bs[(kb8 + fc + 4) * 72 + n]);
            }
#pragma unroll
            for (int mf = 0; mf < 2; mf++)
#pragma unroll
                for (int nf = 0; nf < 4; nf++)
                    mma_tf32(acc[mf][nf], afr[mf], bfr[nf]);
        }
        // no trailing sync: next iteration's wait+sync orders buffer reuse
    }

#pragma unroll
    for (int mf = 0; mf < 2; mf++) {
#pragma unroll
        for (int half = 0; half < 2; half++) {
            int row = bm + wm * 32 + mf * 16 + fr + half * 8;
#pragma unroll
            for (int nf = 0; nf < 4; nf++) {
                int col = bn + wn * 32 + nf * 8 + 2 * fc;
                float v0 = acc[mf][nf][half * 2 + 0] + bias[col];
                float v1 = acc[mf][nf][half * 2 + 1] + bias[col + 1];
                if (EPI == 1) {
                    v0 = 0.5f * v0 * (1.0f + erff(v0 * 0.70710678118654752f));
                    v1 = 0.5f * v1 * (1.0f + erff(v1 * 0.70710678118654752f));
                }
                if (EPI == 2) {
                    float2 r2 = *(const float2*)&res[(size_t)row * N + col];
                    v0 += r2.x; v1 += r2.y;
                }
                float2 o; o.x = v0; o.y = v1;
                *(float2*)&C[(size_t)row * N + col] = o;
            }
        }
    }
}

// ---------------- tf32 flash attention, double-buffered K/V cp.async --------
// dyn smem floats: Q[64*68] | K[2][32*68] | V[2][32*72] | P[64*36]
#define AT_Q 0
#define AT_K 4352
#define AT_V 8704
#define AT_P 13312
#define ATTN_SMEM (15616 * 4)

__global__ __launch_bounds__(128) void attn_tc(
    const float* __restrict__ qkv, float* __restrict__ out)
{
    extern __shared__ float sm[];

    const int bh = blockIdx.y;
    const int b = bh / HEADS, h = bh % HEADS;
    const int q0 = blockIdx.x * 64;
    const int tid = threadIdx.x;
    const int lane = tid & 31;
    const int wid = tid >> 5;
    const int fr = lane >> 2, fc = lane & 3;
    const int r0 = wid * 16 + fr;
    const size_t rstride = 3 * DIM;
    const size_t base = (size_t)b * SEQ * rstride + h * DH;

#pragma unroll
    for (int t = 0; t < 8; t++) {
        int q = tid + t * 128;
        int r = q >> 4, dq = (q & 15) * 4;
        float4 v = *(const float4*)&qkv[base + (size_t)(q0 + r) * rstride + dq];
        v.x *= 0.125f; v.y *= 0.125f; v.z *= 0.125f; v.w *= 0.125f;
        *(float4*)&sm[AT_Q + r * 68 + dq] = v;
    }

    auto issue_kv = [&](int kt, int buf) {
#pragma unroll
        for (int t = 0; t < 4; t++) {
            int q = tid + t * 128;
            int r = q >> 4, dq = (q & 15) * 4;
            cpa16(cvta_s(&sm[AT_K + buf * 2176 + r * 68 + dq]),
                  &qkv[base + DIM + (size_t)(kt + r) * rstride + dq]);
            cpa16(cvta_s(&sm[AT_V + buf * 2304 + r * 72 + dq]),
                  &qkv[base + 2 * DIM + (size_t)(kt + r) * rstride + dq]);
        }
        cp_commit();
    };

    issue_kv(0, 0);

    float m0 = -1e30f, m1 = -1e30f, l0 = 0.f, l1 = 0.f;
    float acc_o[8][4];
#pragma unroll
    for (int nf = 0; nf < 8; nf++)
#pragma unroll
        for (int i = 0; i < 4; i++) acc_o[nf][i] = 0.f;

    const int NT = SEQ / 32;
    for (int it = 0; it < NT; it++) {
        const int buf = it & 1;
        __syncthreads();
        if (it + 1 < NT) { issue_kv((it + 1) * 32, buf ^ 1); cp_wait1(); }
        else             { cp_wait0(); }
        __syncthreads();

        const float* Ks = &sm[AT_K + buf * 2176];
        const float* Vs = &sm[AT_V + buf * 2304];

        float s[4][4];
#pragma unroll
        for (int nf = 0; nf < 4; nf++)
#pragma unroll
            for (int i = 0; i < 4; i++) s[nf][i] = 0.f;
#pragma unroll
        for (int ks = 0; ks < 8; ks++) {
            const int kb = ks * 8;
            uint32_t a[4];
            a[0] = __float_as_uint(sm[AT_Q + r0 * 68 + kb + fc]);
            a[1] = __float_as_uint(sm[AT_Q + (r0 + 8) * 68 + kb + fc]);
            a[2] = __float_as_uint(sm[AT_Q + r0 * 68 + kb + fc + 4]);
            a[3] = __float_as_uint(sm[AT_Q + (r0 + 8) * 68 + kb + fc + 4]);
#pragma unroll
            for (int nf = 0; nf < 4; nf++) {
                uint32_t bb[2];
                bb[0] = __float_as_uint(Ks[(nf * 8 + fr) * 68 + kb + fc]);
                bb[1] = __float_as_uint(Ks[(nf * 8 + fr) * 68 + kb + fc + 4]);
                mma_tf32(s[nf], a, bb);
            }
        }

        float mx0 = -1e30f, mx1 = -1e30f;
#pragma unroll
        for (int nf = 0; nf < 4; nf++) {
            mx0 = fmaxf(mx0, fmaxf(s[nf][0], s[nf][1]));
            mx1 = fmaxf(mx1, fmaxf(s[nf][2], s[nf][3]));
        }
        mx0 = fmaxf(mx0, __shfl_xor_sync(0xffffffffu, mx0, 1));
        mx0 = fmaxf(mx0, __shfl_xor_sync(0xffffffffu, mx0, 2));
        mx1 = fmaxf(mx1, __shfl_xor_sync(0xffffffffu, mx1, 1));
        mx1 = fmaxf(mx1, __shfl_xor_sync(0xffffffffu, mx1, 2));
        float mn0 = fmaxf(m0, mx0), mn1 = fmaxf(m1, mx1);
        float al0 = __expf(m0 - mn0), al1 = __expf(m1 - mn1);
        float sum0 = 0.f, sum1 = 0.f;
#pragma unroll
        for (int nf = 0; nf < 4; nf++) {
            s[nf][0] = __expf(s[nf][0] - mn0);
            s[nf][1] = __expf(s[nf][1] - mn0);
            s[nf][2] = __expf(s[nf][2] - mn1);
            s[nf][3] = __expf(s[nf][3] - mn1);
            sum0 += s[nf][0] + s[nf][1];
            sum1 += s[nf][2] + s[nf][3];
        }
        sum0 += __shfl_xor_sync(0xffffffffu, sum0, 1);
        sum0 += __shfl_xor_sync(0xffffffffu, sum0, 2);
        sum1 += __shfl_xor_sync(0xffffffffu, sum1, 1);
        sum1 += __shfl_xor_sync(0xffffffffu, sum1, 2);
        l0 = l0 * al0 + sum0; l1 = l1 * al1 + sum1;
        m0 = mn0; m1 = mn1;
#pragma unroll
        for (int nf = 0; nf < 8; nf++) {
            acc_o[nf][0] *= al0; acc_o[nf][1] *= al0;
            acc_o[nf][2] *= al1; acc_o[nf][3] *= al1;
        }

#pragma unroll
        for (int nf = 0; nf < 4; nf++) {
            float2 p01; p01.x = s[nf][0]; p01.y = s[nf][1];
            float2 p23; p23.x = s[nf][2]; p23.y = s[nf][3];
            *(float2*)&sm[AT_P + r0 * 36 + nf * 8 + 2 * fc]       = p01;
            *(float2*)&sm[AT_P + (r0 + 8) * 36 + nf * 8 + 2 * fc] = p23;
        }
        __syncwarp();

#pragma unroll
        for (int ks = 0; ks < 4; ks++) {
            const int kb = ks * 8;
            uint32_t a[4];
            a[0] = __float_as_uint(sm[AT_P + r0 * 36 + kb + fc]);
            a[1] = __float_as_uint(sm[AT_P + (r0 + 8) * 36 + kb + fc]);
            a[2] = __float_as_uint(sm[AT_P + r0 * 36 + kb + fc + 4]);
            a[3] = __float_as_uint(sm[AT_P + (r0 + 8) * 36 + kb + fc + 4]);
#pragma unroll
            for (int nf = 0; nf < 8; nf++) {
                uint32_t bb[2];
                bb[0] = __float_as_uint(Vs[(kb + fc) * 72 + nf * 8 + fr]);
                bb[1] = __float_as_uint(Vs[(kb + fc + 4) * 72 + nf * 8 + fr]);
                mma_tf32(acc_o[nf], a, bb);
            }
        }
    }

    float inv0 = 1.0f / l0, inv1 = 1.0f / l1;
    const size_t obase = (size_t)(b * SEQ) * DIM + h * DH;
#pragma unroll
    for (int nf = 0; nf < 8; nf++) {
        int col = nf * 8 + 2 * fc;
        float2 o0; o0.x = acc_o[nf][0] * inv0; o0.y = acc_o[nf][1] * inv0;
        float2 o1; o1.x = acc_o[nf][2] * inv1; o1.y = acc_o[nf][3] * inv1;
        *(float2*)&out[obase + (size_t)(q0 + r0) * DIM + col]     = o0;
        *(float2*)&out[obase + (size_t)(q0 + r0 + 8) * DIM + col] = o1;
    }
}

// ---------------- launch ----------------------------------------------------
extern "C" void kernel_launch(void* const* d_in, const int* in_sizes, int n_in,
                              void* d_out, int out_size)
{
    const float* x      = (const float*)d_in[0];
    const float* w_qkv  = (const float*)d_in[1];
    const float* b_qkv  = (const float*)d_in[2];
    const float* w_proj = (const float*)d_in[3];
    const float* b_proj = (const float*)d_in[4];
    const float* w_fc1  = (const float*)d_in[5];
    const float* b_fc1  = (const float*)d_in[6];
    const float* w_fc2  = (const float*)d_in[7];
    const float* b_fc2  = (const float*)d_in[8];
    const float* g1     = (const float*)d_in[9];
    const float* beta1  = (const float*)d_in[10];
    const float* g2     = (const float*)d_in[11];
    const float* beta2  = (const float*)d_in[12];
    float* out = (float*)d_out;

    float *p_ln, *p_qkv, *p_attn, *p_x1, *p_h;
    cudaGetSymbolAddress((void**)&p_ln,   g_ln);
    cudaGetSymbolAddress((void**)&p_qkv,  g_qkv);
    cudaGetSymbolAddress((void**)&p_attn, g_attn);
    cudaGetSymbolAddress((void**)&p_x1,   g_x1);
    cudaGetSymbolAddress((void**)&p_h,    g_h);

    cudaFuncSetAttribute(gemm_tc<0>, cudaFuncAttributeMaxDynamicSharedMemorySize, GEMM_SMEM);
    cudaFuncSetAttribute(gemm_tc<1>, cudaFuncAttributeMaxDynamicSharedMemorySize, GEMM_SMEM);
    cudaFuncSetAttribute(gemm_tc<2>, cudaFuncAttributeMaxDynamicSharedMemorySize, GEMM_SMEM);
    cudaFuncSetAttribute(attn_tc,    cudaFuncAttributeMaxDynamicSharedMemorySize, ATTN_SMEM);

    // 1) LN1
    ln_kernel<<<NTOK / 8, 256>>>(x, g1, beta1, p_ln);
    // 2) QKV GEMM: [8192,384] @ [384,1152] + bias
    gemm_tc<0><<<dim3(3 * DIM / 64, NTOK / 128), 256, GEMM_SMEM>>>(
        p_ln, w_qkv, b_qkv, nullptr, p_qkv, NTOK, DIM, 3 * DIM);
    // 3) tf32 flash attention
    attn_tc<<<dim3(SEQ / 64, BATCH * HEADS), 128, ATTN_SMEM>>>(p_qkv, p_attn);
    // 4) proj GEMM + bias + residual(x)
    gemm_tc<2><<<dim3(DIM / 64, NTOK / 128), 256, GEMM_SMEM>>>(
        p_attn, w_proj, b_proj, x, p_x1, NTOK, DIM, DIM);
    // 5) LN2
    ln_kernel<<<NTOK / 8, 256>>>(p_x1, g2, beta2, p_ln);
    // 6) FC1 GEMM + bias + exact GELU
    gemm_tc<1><<<dim3(HID / 64, NTOK / 128), 256, GEMM_SMEM>>>(
        p_ln, w_fc1, b_fc1, nullptr, p_h, NTOK, DIM, HID);
    // 7) FC2 GEMM + bias + residual(x1) -> d_out
    gemm_tc<2><<<dim3(DIM / 64, NTOK / 128), 256, GEMM_SMEM>>>(
        p_h, w_fc2, b_fc2, p_x1, out, NTOK, HID, DIM);
}

// round 13
// speedup vs baseline: 1.0263x; 1.0263x over previous
#include <cuda_runtime.h>
#include <math.h>
#include <stdint.h>

#define DIM   384
#define HID   1536
#define BATCH 4
#define SEQ   2048
#define NTOK  (BATCH*SEQ)   /* 8192 tokens */
#define HEADS 6
#define DH    64

// ---------------- scratch (device globals; no allocation allowed) ----------
__device__ float g_ln  [NTOK * DIM];
__device__ float g_qkv [NTOK * 3 * DIM];
__device__ float g_attn[NTOK * DIM];
__device__ float g_x1  [NTOK * DIM];
__device__ float g_h   [NTOK * HID];

// ---------------- helpers ---------------------------------------------------
__device__ __forceinline__ void mma_tf32(float c[4], const uint32_t a[4], const uint32_t b[2]) {
    asm volatile(
        "mma.sync.aligned.m16n8k8.row.col.f32.tf32.tf32.f32 "
        "{%0,%1,%2,%3}, {%4,%5,%6,%7}, {%8,%9}, {%0,%1,%2,%3};"
        : "+f"(c[0]), "+f"(c[1]), "+f"(c[2]), "+f"(c[3])
        : "r"(a[0]), "r"(a[1]), "r"(a[2]), "r"(a[3]), "r"(b[0]), "r"(b[1]));
}
__device__ __forceinline__ uint32_t cvta_s(const void* p) {
    return (uint32_t)__cvta_generic_to_shared(p);
}
__device__ __forceinline__ void cpa16(uint32_t dst, const void* src) {
    asm volatile("cp.async.cg.shared.global [%0], [%1], 16;" :: "r"(dst), "l"(src));
}
__device__ __forceinline__ void cp_commit() { asm volatile("cp.async.commit_group;"); }
__device__ __forceinline__ void cp_wait2()  { asm volatile("cp.async.wait_group 2;"); }
__device__ __forceinline__ void cp_wait1()  { asm volatile("cp.async.wait_group 1;"); }
__device__ __forceinline__ void cp_wait0()  { asm volatile("cp.async.wait_group 0;"); }

// ---------------- LayerNorm: one warp per 384-elem row ---------------------
__global__ __launch_bounds__(256) void ln_kernel(
    const float* __restrict__ x, const float* __restrict__ g,
    const float* __restrict__ b, float* __restrict__ out)
{
    int warp = (blockIdx.x * blockDim.x + threadIdx.x) >> 5;
    int lane = threadIdx.x & 31;
    if (warp >= NTOK) return;
    const float* xr = x + (size_t)warp * DIM;

    float v[12];
    float s = 0.f;
#pragma unroll
    for (int i = 0; i < 12; i++) { v[i] = xr[lane + i * 32]; s += v[i]; }
#pragma unroll
    for (int o = 16; o > 0; o >>= 1) s += __shfl_xor_sync(0xffffffffu, s, o);
    float mu = s * (1.0f / DIM);
    float vs = 0.f;
#pragma unroll
    for (int i = 0; i < 12; i++) { float d = v[i] - mu; vs += d * d; }
#pragma unroll
    for (int o = 16; o > 0; o >>= 1) vs += __shfl_xor_sync(0xffffffffu, vs, o);
    float rstd = rsqrtf(vs * (1.0f / DIM) + 1e-6f);

    float* orow = out + (size_t)warp * DIM;
#pragma unroll
    for (int i = 0; i < 12; i++) {
        int c = lane + i * 32;
        orow[c] = (v[i] - mu) * rstd * g[c] + b[c];
    }
}

// ---------------- tf32 GEMM: 128x64 tile, 4-stage cp.async ------------------
// A [M][K] row-major, W [K][N] row-major. Per stage: As[128][36] + Bs[32][72].
// 256 threads = 8 warps (4 wm x 2 wn), warp tile 32x32.
#define ASTG   (128 * 36)
#define BSTG   (32 * 72)
#define STGF   (ASTG + BSTG)
#define NSTAGE 4
#define GEMM_SMEM (NSTAGE * STGF * 4)   /* 110592 bytes */

template <int EPI>
__global__ __launch_bounds__(256, 2) void gemm_tc(
    const float* __restrict__ A, const float* __restrict__ W,
    const float* __restrict__ bias, const float* __restrict__ res,
    float* __restrict__ C, int M, int K, int N)
{
    extern __shared__ float smem[];

    const int tid  = threadIdx.x;
    const int lane = tid & 31;
    const int wid  = tid >> 5;
    const int wm   = wid & 3;
    const int wn   = wid >> 2;
    const int bm   = blockIdx.y * 128;
    const int bn   = blockIdx.x * 64;

    const int a_kq = (tid & 7) << 2;
    const int a_mr = tid >> 3;
    const int b_r  = tid >> 3;
    const int b_q  = tid & 7;
    const int fr   = lane >> 2;
    const int fc   = lane & 3;

    float acc[2][4][4];
#pragma unroll
    for (int mf = 0; mf < 2; mf++)
#pragma unroll
        for (int nf = 0; nf < 4; nf++)
#pragma unroll
            for (int i = 0; i < 4; i++) acc[mf][nf][i] = 0.f;

    const int NK = K >> 5;

    auto issue = [&](int kb) {
        float* dst = smem + (kb % NSTAGE) * STGF;
        const int k0 = kb << 5;
#pragma unroll
        for (int mi = 0; mi < 4; mi++) {
            int m = mi * 32 + a_mr;
            cpa16(cvta_s(dst + m * 36 + a_kq), &A[(size_t)(bm + m) * K + k0 + a_kq]);
        }
        cpa16(cvta_s(dst + ASTG + b_r * 72 + b_q * 4),
              &W[(size_t)(k0 + b_r) * N + bn + b_q * 4]);
        cpa16(cvta_s(dst + ASTG + b_r * 72 + (b_q + 8) * 4),
              &W[(size_t)(k0 + b_r) * N + bn + (b_q + 8) * 4]);
        cp_commit();
    };

    issue(0);
    if (NK > 1) issue(1);
    if (NK > 2) issue(2);

    for (int kb = 0; kb < NK; kb++) {
        const int pend = NK - 1 - kb;
        if (pend >= 3)      cp_wait2();
        else if (pend == 2) cp_wait2();
        else if (pend == 1) cp_wait1();
        else                cp_wait0();
        __syncthreads();
        if (kb + 3 < NK) issue(kb + 3);

        const float* As = smem + (kb % NSTAGE) * STGF;
        const float* Bs = As + ASTG;

#pragma unroll
        for (int ks = 0; ks < 4; ks++) {
            const int kb8 = ks * 8;
            uint32_t afr[2][4], bfr[4][2];
#pragma unroll
            for (int mf = 0; mf < 2; mf++) {
                int r = wm * 32 + mf * 16 + fr;
                int c = kb8 + fc;
                afr[mf][0] = __float_as_uint(As[r * 36 + c]);
                afr[mf][1] = __float_as_uint(As[(r + 8) * 36 + c]);
                afr[mf][2] = __float_as_uint(As[r * 36 + c + 4]);
                afr[mf][3] = __float_as_uint(As[(r + 8) * 36 + c + 4]);
            }
#pragma unroll
            for (int nf = 0; nf < 4; nf++) {
                int n = wn * 32 + nf * 8 + fr;
                bfr[nf][0] = __float_as_uint(Bs[(kb8 + fc) * 72 + n]);
                bfr[nf][1] = __float_as_uint(Bs[(kb8 + fc + 4) * 72 + n]);
            }
#pragma unroll
            for (int mf = 0; mf < 2; mf++)
#pragma unroll
                for (int nf = 0; nf < 4; nf++)
                    mma_tf32(acc[mf][nf], afr[mf], bfr[nf]);
        }
    }

#pragma unroll
    for (int mf = 0; mf < 2; mf++) {
#pragma unroll
        for (int half = 0; half < 2; half++) {
            int row = bm + wm * 32 + mf * 16 + fr + half * 8;
#pragma unroll
            for (int nf = 0; nf < 4; nf++) {
                int col = bn + wn * 32 + nf * 8 + 2 * fc;
                float v0 = acc[mf][nf][half * 2 + 0] + bias[col];
                float v1 = acc[mf][nf][half * 2 + 1] + bias[col + 1];
                if (EPI == 1) {
                    v0 = 0.5f * v0 * (1.0f + erff(v0 * 0.70710678118654752f));
                    v1 = 0.5f * v1 * (1.0f + erff(v1 * 0.70710678118654752f));
                }
                if (EPI == 2) {
                    float2 r2 = *(const float2*)&res[(size_t)row * N + col];
                    v0 += r2.x; v1 += r2.y;
                }
                float2 o; o.x = v0; o.y = v1;
                *(float2*)&C[(size_t)row * N + col] = o;
            }
        }
    }
}

// ---------------- tf32 flash attention: 128 q-rows, 256 thr, dbuf K/V -------
// dyn smem floats: Q[128*68] | K[2][32*68] | V[2][32*72] | P[128*36]
#define AT_Q 0
#define AT_K 8704
#define AT_V 13056
#define AT_P 17664
#define ATTN_SMEM (22272 * 4)   /* 89088 bytes */

__global__ __launch_bounds__(256, 2) void attn_tc(
    const float* __restrict__ qkv, float* __restrict__ out)
{
    extern __shared__ float sm[];

    const int bh = blockIdx.y;
    const int b = bh / HEADS, h = bh % HEADS;
    const int q0 = blockIdx.x * 128;
    const int tid = threadIdx.x;
    const int lane = tid & 31;
    const int wid = tid >> 5;
    const int fr = lane >> 2, fc = lane & 3;
    const int r0 = wid * 16 + fr;           // warp owns q-rows [16w,16w+16)
    const size_t rstride = 3 * DIM;
    const size_t base = (size_t)b * SEQ * rstride + h * DH;

    // load Q (128x64), fold in softmax scale (mma HW truncates to tf32)
#pragma unroll
    for (int t = 0; t < 8; t++) {
        int q = tid + t * 256;
        int r = q >> 4, dq = (q & 15) * 4;
        float4 v = *(const float4*)&qkv[base + (size_t)(q0 + r) * rstride + dq];
        v.x *= 0.125f; v.y *= 0.125f; v.z *= 0.125f; v.w *= 0.125f;
        *(float4*)&sm[AT_Q + r * 68 + dq] = v;
    }

    auto issue_kv = [&](int kt, int buf) {
#pragma unroll
        for (int t = 0; t < 2; t++) {
            int q = tid + t * 256;
            int r = q >> 4, dq = (q & 15) * 4;
            cpa16(cvta_s(&sm[AT_K + buf * 2176 + r * 68 + dq]),
                  &qkv[base + DIM + (size_t)(kt + r) * rstride + dq]);
            cpa16(cvta_s(&sm[AT_V + buf * 2304 + r * 72 + dq]),
                  &qkv[base + 2 * DIM + (size_t)(kt + r) * rstride + dq]);
        }
        cp_commit();
    };

    issue_kv(0, 0);

    float m0 = -1e30f, m1 = -1e30f, l0 = 0.f, l1 = 0.f;
    float acc_o[8][4];
#pragma unroll
    for (int nf = 0; nf < 8; nf++)
#pragma unroll
        for (int i = 0; i < 4; i++) acc_o[nf][i] = 0.f;

    const int NT = SEQ / 32;
    for (int it = 0; it < NT; it++) {
        const int buf = it & 1;
        __syncthreads();                 // everyone done reading buf^1
        if (it + 1 < NT) { issue_kv((it + 1) * 32, buf ^ 1); cp_wait1(); }
        else             { cp_wait0(); }
        __syncthreads();                 // tile it visible

        const float* Ks = &sm[AT_K + buf * 2176];
        const float* Vs = &sm[AT_V + buf * 2304];

        float s[4][4];
#pragma unroll
        for (int nf = 0; nf < 4; nf++)
#pragma unroll
            for (int i = 0; i < 4; i++) s[nf][i] = 0.f;
#pragma unroll
        for (int ks = 0; ks < 8; ks++) {
            const int kb = ks * 8;
            uint32_t a[4];
            a[0] = __float_as_uint(sm[AT_Q + r0 * 68 + kb + fc]);
            a[1] = __float_as_uint(sm[AT_Q + (r0 + 8) * 68 + kb + fc]);
            a[2] = __float_as_uint(sm[AT_Q + r0 * 68 + kb + fc + 4]);
            a[3] = __float_as_uint(sm[AT_Q + (r0 + 8) * 68 + kb + fc + 4]);
#pragma unroll
            for (int nf = 0; nf < 4; nf++) {
                uint32_t bb[2];
                bb[0] = __float_as_uint(Ks[(nf * 8 + fr) * 68 + kb + fc]);
                bb[1] = __float_as_uint(Ks[(nf * 8 + fr) * 68 + kb + fc + 4]);
                mma_tf32(s[nf], a, bb);
            }
        }

        float mx0 = -1e30f, mx1 = -1e30f;
#pragma unroll
        for (int nf = 0; nf < 4; nf++) {
            mx0 = fmaxf(mx0, fmaxf(s[nf][0], s[nf][1]));
            mx1 = fmaxf(mx1, fmaxf(s[nf][2], s[nf][3]));
        }
        mx0 = fmaxf(mx0, __shfl_xor_sync(0xffffffffu, mx0, 1));
        mx0 = fmaxf(mx0, __shfl_xor_sync(0xffffffffu, mx0, 2));
        mx1 = fmaxf(mx1, __shfl_xor_sync(0xffffffffu, mx1, 1));
        mx1 = fmaxf(mx1, __shfl_xor_sync(0xffffffffu, mx1, 2));
        float mn0 = fmaxf(m0, mx0), mn1 = fmaxf(m1, mx1);
        float al0 = __expf(m0 - mn0), al1 = __expf(m1 - mn1);
        float sum0 = 0.f, sum1 = 0.f;
#pragma unroll
        for (int nf = 0; nf < 4; nf++) {
            s[nf][0] = __expf(s[nf][0] - mn0);
            s[nf][1] = __expf(s[nf][1] - mn0);
            s[nf][2] = __expf(s[nf][2] - mn1);
            s[nf][3] = __expf(s[nf][3] - mn1);
            sum0 += s[nf][0] + s[nf][1];
            sum1 += s[nf][2] + s[nf][3];
        }
        sum0 += __shfl_xor_sync(0xffffffffu, sum0, 1);
        sum0 += __shfl_xor_sync(0xffffffffu, sum0, 2);
        sum1 += __shfl_xor_sync(0xffffffffu, sum1, 1);
        sum1 += __shfl_xor_sync(0xffffffffu, sum1, 2);
        l0 = l0 * al0 + sum0; l1 = l1 * al1 + sum1;
        m0 = mn0; m1 = mn1;
#pragma unroll
        for (int nf = 0; nf < 8; nf++) {
            acc_o[nf][0] *= al0; acc_o[nf][1] *= al0;
            acc_o[nf][2] *= al1; acc_o[nf][3] *= al1;
        }

        // stage P (warp-private rows)
#pragma unroll
        for (int nf = 0; nf < 4; nf++) {
            float2 p01; p01.x = s[nf][0]; p01.y = s[nf][1];
            float2 p23; p23.x = s[nf][2]; p23.y = s[nf][3];
            *(float2*)&sm[AT_P + r0 * 36 + nf * 8 + 2 * fc]       = p01;
            *(float2*)&sm[AT_P + (r0 + 8) * 36 + nf * 8 + 2 * fc] = p23;
        }
        __syncwarp();

#pragma unroll
        for (int ks = 0; ks < 4; ks++) {
            const int kb = ks * 8;
            uint32_t a[4];
            a[0] = __float_as_uint(sm[AT_P + r0 * 36 + kb + fc]);
            a[1] = __float_as_uint(sm[AT_P + (r0 + 8) * 36 + kb + fc]);
            a[2] = __float_as_uint(sm[AT_P + r0 * 36 + kb + fc + 4]);
            a[3] = __float_as_uint(sm[AT_P + (r0 + 8) * 36 + kb + fc + 4]);
#pragma unroll
            for (int nf = 0; nf < 8; nf++) {
                uint32_t bb[2];
                bb[0] = __float_as_uint(Vs[(kb + fc) * 72 + nf * 8 + fr]);
                bb[1] = __float_as_uint(Vs[(kb + fc + 4) * 72 + nf * 8 + fr]);
                mma_tf32(acc_o[nf], a, bb);
            }
        }
    }

    float inv0 = 1.0f / l0, inv1 = 1.0f / l1;
    const size_t obase = (size_t)(b * SEQ) * DIM + h * DH;
#pragma unroll
    for (int nf = 0; nf < 8; nf++) {
        int col = nf * 8 + 2 * fc;
        float2 o0; o0.x = acc_o[nf][0] * inv0; o0.y = acc_o[nf][1] * inv0;
        float2 o1; o1.x = acc_o[nf][2] * inv1; o1.y = acc_o[nf][3] * inv1;
        *(float2*)&out[obase + (size_t)(q0 + r0) * DIM + col]     = o0;
        *(float2*)&out[obase + (size_t)(q0 + r0 + 8) * DIM + col] = o1;
    }
}

// ---------------- launch ----------------------------------------------------
extern "C" void kernel_launch(void* const* d_in, const int* in_sizes, int n_in,
                              void* d_out, int out_size)
{
    const float* x      = (const float*)d_in[0];
    const float* w_qkv  = (const float*)d_in[1];
    const float* b_qkv  = (const float*)d_in[2];
    const float* w_proj = (const float*)d_in[3];
    const float* b_proj = (const float*)d_in[4];
    const float* w_fc1  = (const float*)d_in[5];
    const float* b_fc1  = (const float*)d_in[6];
    const float* w_fc2  = (const float*)d_in[7];
    const float* b_fc2  = (const float*)d_in[8];
    const float* g1     = (const float*)d_in[9];
    const float* beta1  = (const float*)d_in[10];
    const float* g2     = (const float*)d_in[11];
    const float* beta2  = (const float*)d_in[12];
    float* out = (float*)d_out;

    float *p_ln, *p_qkv, *p_attn, *p_x1, *p_h;
    cudaGetSymbolAddress((void**)&p_ln,   g_ln);
    cudaGetSymbolAddress((void**)&p_qkv,  g_qkv);
    cudaGetSymbolAddress((void**)&p_attn, g_attn);
    cudaGetSymbolAddress((void**)&p_x1,   g_x1);
    cudaGetSymbolAddress((void**)&p_h,    g_h);

    cudaFuncSetAttribute(gemm_tc<0>, cudaFuncAttributeMaxDynamicSharedMemorySize, GEMM_SMEM);
    cudaFuncSetAttribute(gemm_tc<1>, cudaFuncAttributeMaxDynamicSharedMemorySize, GEMM_SMEM);
    cudaFuncSetAttribute(gemm_tc<2>, cudaFuncAttributeMaxDynamicSharedMemorySize, GEMM_SMEM);
    cudaFuncSetAttribute(attn_tc,    cudaFuncAttributeMaxDynamicSharedMemorySize, ATTN_SMEM);

    // 1) LN1
    ln_kernel<<<NTOK / 8, 256>>>(x, g1, beta1, p_ln);
    // 2) QKV GEMM: [8192,384] @ [384,1152] + bias
    gemm_tc<0><<<dim3(3 * DIM / 64, NTOK / 128), 256, GEMM_SMEM>>>(
        p_ln, w_qkv, b_qkv, nullptr, p_qkv, NTOK, DIM, 3 * DIM);
    // 3) tf32 flash attention (128 q-rows per CTA)
    attn_tc<<<dim3(SEQ / 128, BATCH * HEADS), 256, ATTN_SMEM>>>(p_qkv, p_attn);
    // 4) proj GEMM + bias + residual(x)
    gemm_tc<2><<<dim3(DIM / 64, NTOK / 128), 256, GEMM_SMEM>>>(
        p_attn, w_proj, b_proj, x, p_x1, NTOK, DIM, DIM);
    // 5) LN2
    ln_kernel<<<NTOK / 8, 256>>>(p_x1, g2, beta2, p_ln);
    // 6) FC1 GEMM + bias + exact GELU
    gemm_tc<1><<<dim3(HID / 64, NTOK / 128), 256, GEMM_SMEM>>>(
        p_ln, w_fc1, b_fc1, nullptr, p_h, NTOK, DIM, HID);
    // 7) FC2 GEMM + bias + residual(x1) -> d_out
    gemm_tc<2><<<dim3(DIM / 64, NTOK / 128), 256, GEMM_SMEM>>>(
        p_h, w_fc2, b_fc2, p_x1, out, NTOK, HID, DIM);
}

// round 15
// speedup vs baseline: 1.0718x; 1.0444x over previous
#include <cuda_runtime.h>
#include <math.h>
#include <stdint.h>

#define DIM   384
#define HID   1536
#define BATCH 4
#define SEQ   2048
#define NTOK  (BATCH*SEQ)   /* 8192 tokens */
#define HEADS 6
#define DH    64

// ---------------- scratch (device globals; no allocation allowed) ----------
__device__ float g_ln  [NTOK * DIM];
__device__ float g_qkv [NTOK * 3 * DIM];
__device__ float g_attn[NTOK * DIM];
__device__ float g_x1  [NTOK * DIM];
__device__ float g_h   [NTOK * HID];

// ---------------- helpers ---------------------------------------------------
__device__ __forceinline__ void mma_tf32(float c[4], const uint32_t a[4], const uint32_t b[2]) {
    asm volatile(
        "mma.sync.aligned.m16n8k8.row.col.f32.tf32.tf32.f32 "
        "{%0,%1,%2,%3}, {%4,%5,%6,%7}, {%8,%9}, {%0,%1,%2,%3};"
        : "+f"(c[0]), "+f"(c[1]), "+f"(c[2]), "+f"(c[3])
        : "r"(a[0]), "r"(a[1]), "r"(a[2]), "r"(a[3]), "r"(b[0]), "r"(b[1]));
}
__device__ __forceinline__ uint32_t cvta_s(const void* p) {
    return (uint32_t)__cvta_generic_to_shared(p);
}
__device__ __forceinline__ void cpa16(uint32_t dst, const void* src) {
    asm volatile("cp.async.cg.shared.global [%0], [%1], 16;" :: "r"(dst), "l"(src));
}
__device__ __forceinline__ void cp_commit() { asm volatile("cp.async.commit_group;"); }
__device__ __forceinline__ void cp_wait1()  { asm volatile("cp.async.wait_group 1;"); }
__device__ __forceinline__ void cp_wait0()  { asm volatile("cp.async.wait_group 0;"); }

// ---------------- LayerNorm: one warp per 384-elem row ---------------------
__global__ __launch_bounds__(256) void ln_kernel(
    const float* __restrict__ x, const float* __restrict__ g,
    const float* __restrict__ b, float* __restrict__ out)
{
    int warp = (blockIdx.x * blockDim.x + threadIdx.x) >> 5;
    int lane = threadIdx.x & 31;
    if (warp >= NTOK) return;
    const float* xr = x + (size_t)warp * DIM;

    float v[12];
    float s = 0.f;
#pragma unroll
    for (int i = 0; i < 12; i++) { v[i] = xr[lane + i * 32]; s += v[i]; }
#pragma unroll
    for (int o = 16; o > 0; o >>= 1) s += __shfl_xor_sync(0xffffffffu, s, o);
    float mu = s * (1.0f / DIM);
    float vs = 0.f;
#pragma unroll
    for (int i = 0; i < 12; i++) { float d = v[i] - mu; vs += d * d; }
#pragma unroll
    for (int o = 16; o > 0; o >>= 1) vs += __shfl_xor_sync(0xffffffffu, vs, o);
    float rstd = rsqrtf(vs * (1.0f / DIM) + 1e-6f);

    float* orow = out + (size_t)warp * DIM;
#pragma unroll
    for (int i = 0; i < 12; i++) {
        int c = lane + i * 32;
        orow[c] = (v[i] - mu) * rstd * g[c] + b[c];
    }
}

// ---------------- tf32 GEMM: 128x64 tile, 2-stage (R5 pattern), 3 CTAs/SM ---
// A [M][K] row-major, W [K][N] row-major. Per stage: As[128][36] + Bs[32][72].
// 256 threads = 8 warps (4 wm x 2 wn), warp tile 32x32.
#define ASTG   (128 * 36)
#define BSTG   (32 * 72)
#define STGF   (ASTG + BSTG)
#define GEMM_SMEM (2 * STGF * 4)   /* 55296 bytes */

template <int EPI>
__global__ __launch_bounds__(256, 3) void gemm_tc(
    const float* __restrict__ A, const float* __restrict__ W,
    const float* __restrict__ bias, const float* __restrict__ res,
    float* __restrict__ C, int M, int K, int N)
{
    extern __shared__ float smem[];

    const int tid  = threadIdx.x;
    const int lane = tid & 31;
    const int wid  = tid >> 5;
    const int wm   = wid & 3;
    const int wn   = wid >> 2;
    const int bm   = blockIdx.y * 128;
    const int bn   = blockIdx.x * 64;

    const int a_kq = (tid & 7) << 2;
    const int a_mr = tid >> 3;
    const int b_r  = tid >> 3;
    const int b_q  = tid & 7;
    const int fr   = lane >> 2;
    const int fc   = lane & 3;

    float acc[2][4][4];
#pragma unroll
    for (int mf = 0; mf < 2; mf++)
#pragma unroll
        for (int nf = 0; nf < 4; nf++)
#pragma unroll
            for (int i = 0; i < 4; i++) acc[mf][nf][i] = 0.f;

    const int NK = K >> 5;

    auto issue = [&](int kb) {
        float* dst = smem + (kb & 1) * STGF;
        const int k0 = kb << 5;
#pragma unroll
        for (int mi = 0; mi < 4; mi++) {
            int m = mi * 32 + a_mr;
            cpa16(cvta_s(dst + m * 36 + a_kq), &A[(size_t)(bm + m) * K + k0 + a_kq]);
        }
        cpa16(cvta_s(dst + ASTG + b_r * 72 + b_q * 4),
              &W[(size_t)(k0 + b_r) * N + bn + b_q * 4]);
        cpa16(cvta_s(dst + ASTG + b_r * 72 + (b_q + 8) * 4),
              &W[(size_t)(k0 + b_r) * N + bn + (b_q + 8) * 4]);
        cp_commit();
    };

    issue(0);

    for (int kb = 0; kb < NK; kb++) {
        // issue next stage into buf^1 (safe: trailing sync of previous iter)
        if (kb + 1 < NK) { issue(kb + 1); cp_wait1(); }
        else             { cp_wait0(); }
        __syncthreads();

        const float* As = smem + (kb & 1) * STGF;
        const float* Bs = As + ASTG;

#pragma unroll
        for (int ks = 0; ks < 4; ks++) {
            const int kb8 = ks * 8;
            uint32_t afr[2][4], bfr[4][2];
#pragma unroll
            for (int mf = 0; mf < 2; mf++) {
                int r = wm * 32 + mf * 16 + fr;
                int c = kb8 + fc;
                afr[mf][0] = __float_as_uint(As[r * 36 + c]);
                afr[mf][1] = __float_as_uint(As[(r + 8) * 36 + c]);
                afr[mf][2] = __float_as_uint(As[r * 36 + c + 4]);
                afr[mf][3] = __float_as_uint(As[(r + 8) * 36 + c + 4]);
            }
#pragma unroll
            for (int nf = 0; nf < 4; nf++) {
                int n = wn * 32 + nf * 8 + fr;
                bfr[nf][0] = __float_as_uint(Bs[(kb8 + fc) * 72 + n]);
                bfr[nf][1] = __float_as_uint(Bs[(kb8 + fc + 4) * 72 + n]);
            }
#pragma unroll
            for (int mf = 0; mf < 2; mf++)
#pragma unroll
                for (int nf = 0; nf < 4; nf++)
                    mma_tf32(acc[mf][nf], afr[mf], bfr[nf]);
        }
        __syncthreads();   // protects buf^1 before next iteration's issue
    }

#pragma unroll
    for (int mf = 0; mf < 2; mf++) {
#pragma unroll
        for (int half = 0; half < 2; half++) {
            int row = bm + wm * 32 + mf * 16 + fr + half * 8;
#pragma unroll
            for (int nf = 0; nf < 4; nf++) {
                int col = bn + wn * 32 + nf * 8 + 2 * fc;
                float v0 = acc[mf][nf][half * 2 + 0] + bias[col];
                float v1 = acc[mf][nf][half * 2 + 1] + bias[col + 1];
                if (EPI == 1) {
                    v0 = 0.5f * v0 * (1.0f + erff(v0 * 0.70710678118654752f));
                    v1 = 0.5f * v1 * (1.0f + erff(v1 * 0.70710678118654752f));
                }
                if (EPI == 2) {
                    float2 r2 = *(const float2*)&res[(size_t)row * N + col];
                    v0 += r2.x; v1 += r2.y;
                }
                float2 o; o.x = v0; o.y = v1;
                *(float2*)&C[(size_t)row * N + col] = o;
            }
        }
    }
}

// ---------------- tf32 flash attention: 128 q-rows, 256 thr, dbuf K/V -------
// dyn smem floats: Q[128*68] | K[2][32*68] | V[2][32*72] | P[128*36]
#define AT_Q 0
#define AT_K 8704
#define AT_V 13056
#define AT_P 17664
#define ATTN_SMEM (22272 * 4)   /* 89088 bytes */

__global__ __launch_bounds__(256, 2) void attn_tc(
    const float* __restrict__ qkv, float* __restrict__ out)
{
    extern __shared__ float sm[];

    const int bh = blockIdx.y;
    const int b = bh / HEADS, h = bh % HEADS;
    const int q0 = blockIdx.x * 128;
    const int tid = threadIdx.x;
    const int lane = tid & 31;
    const int wid = tid >> 5;
    const int fr = lane >> 2, fc = lane & 3;
    const int r0 = wid * 16 + fr;
    const size_t rstride = 3 * DIM;
    const size_t base = (size_t)b * SEQ * rstride + h * DH;

#pragma unroll
    for (int t = 0; t < 8; t++) {
        int q = tid + t * 256;
        int r = q >> 4, dq = (q & 15) * 4;
        float4 v = *(const float4*)&qkv[base + (size_t)(q0 + r) * rstride + dq];
        v.x *= 0.125f; v.y *= 0.125f; v.z *= 0.125f; v.w *= 0.125f;
        *(float4*)&sm[AT_Q + r * 68 + dq] = v;
    }

    auto issue_kv = [&](int kt, int buf) {
#pragma unroll
        for (int t = 0; t < 2; t++) {
            int q = tid + t * 256;
            int r = q >> 4, dq = (q & 15) * 4;
            cpa16(cvta_s(&sm[AT_K + buf * 2176 + r * 68 + dq]),
                  &qkv[base + DIM + (size_t)(kt + r) * rstride + dq]);
            cpa16(cvta_s(&sm[AT_V + buf * 2304 + r * 72 + dq]),
                  &qkv[base + 2 * DIM + (size_t)(kt + r) * rstride + dq]);
        }
        cp_commit();
    };

    issue_kv(0, 0);

    float m0 = -1e30f, m1 = -1e30f, l0 = 0.f, l1 = 0.f;
    float acc_o[8][4];
#pragma unroll
    for (int nf = 0; nf < 8; nf++)
#pragma unroll
        for (int i = 0; i < 4; i++) acc_o[nf][i] = 0.f;

    const int NT = SEQ / 32;
    for (int it = 0; it < NT; it++) {
        const int buf = it & 1;
        __syncthreads();
        if (it + 1 < NT) { issue_kv((it + 1) * 32, buf ^ 1); cp_wait1(); }
        else             { cp_wait0(); }
        __syncthreads();

        const float* Ks = &sm[AT_K + buf * 2176];
        const float* Vs = &sm[AT_V + buf * 2304];

        float s[4][4];
#pragma unroll
        for (int nf = 0; nf < 4; nf++)
#pragma unroll
            for (int i = 0; i < 4; i++) s[nf][i] = 0.f;
#pragma unroll
        for (int ks = 0; ks < 8; ks++) {
            const int kb = ks * 8;
            uint32_t a[4];
            a[0] = __float_as_uint(sm[AT_Q + r0 * 68 + kb + fc]);
            a[1] = __float_as_uint(sm[AT_Q + (r0 + 8) * 68 + kb + fc]);
            a[2] = __float_as_uint(sm[AT_Q + r0 * 68 + kb + fc + 4]);
            a[3] = __float_as_uint(sm[AT_Q + (r0 + 8) * 68 + kb + fc + 4]);
#pragma unroll
            for (int nf = 0; nf < 4; nf++) {
                uint32_t bb[2];
                bb[0] = __float_as_uint(Ks[(nf * 8 + fr) * 68 + kb + fc]);
                bb[1] = __float_as_uint(Ks[(nf * 8 + fr) * 68 + kb + fc + 4]);
                mma_tf32(s[nf], a, bb);
            }
        }

        float mx0 = -1e30f, mx1 = -1e30f;
#pragma unroll
        for (int nf = 0; nf < 4; nf++) {
            mx0 = fmaxf(mx0, fmaxf(s[nf][0], s[nf][1]));
            mx1 = fmaxf(mx1, fmaxf(s[nf][2], s[nf][3]));
        }
        mx0 = fmaxf(mx0, __shfl_xor_sync(0xffffffffu, mx0, 1));
        mx0 = fmaxf(mx0, __shfl_xor_sync(0xffffffffu, mx0, 2));
        mx1 = fmaxf(mx1, __shfl_xor_sync(0xffffffffu, mx1, 1));
        mx1 = fmaxf(mx1, __shfl_xor_sync(0xffffffffu, mx1, 2));
        float mn0 = fmaxf(m0, mx0), mn1 = fmaxf(m1, mx1);
        float al0 = __expf(m0 - mn0), al1 = __expf(m1 - mn1);
        float sum0 = 0.f, sum1 = 0.f;
#pragma unroll
        for (int nf = 0; nf < 4; nf++) {
            s[nf][0] = __expf(s[nf][0] - mn0);
            s[nf][1] = __expf(s[nf][1] - mn0);
            s[nf][2] = __expf(s[nf][2] - mn1);
            s[nf][3] = __expf(s[nf][3] - mn1);
            sum0 += s[nf][0] + s[nf][1];
            sum1 += s[nf][2] + s[nf][3];
        }
        sum0 += __shfl_xor_sync(0xffffffffu, sum0, 1);
        sum0 += __shfl_xor_sync(0xffffffffu, sum0, 2);
        sum1 += __shfl_xor_sync(0xffffffffu, sum1, 1);
        sum1 += __shfl_xor_sync(0xffffffffu, sum1, 2);
        l0 = l0 * al0 + sum0; l1 = l1 * al1 + sum1;
        m0 = mn0; m1 = mn1;
#pragma unroll
        for (int nf = 0; nf < 8; nf++) {
            acc_o[nf][0] *= al0; acc_o[nf][1] *= al0;
            acc_o[nf][2] *= al1; acc_o[nf][3] *= al1;
        }

#pragma unroll
        for (int nf = 0; nf < 4; nf++) {
            float2 p01; p01.x = s[nf][0]; p01.y = s[nf][1];
            float2 p23; p23.x = s[nf][2]; p23.y = s[nf][3];
            *(float2*)&sm[AT_P + r0 * 36 + nf * 8 + 2 * fc]       = p01;
            *(float2*)&sm[AT_P + (r0 + 8) * 36 + nf * 8 + 2 * fc] = p23;
        }
        __syncwarp();

#pragma unroll
        for (int ks = 0; ks < 4; ks++) {
            const int kb = ks * 8;
            uint32_t a[4];
            a[0] = __float_as_uint(sm[AT_P + r0 * 36 + kb + fc]);
            a[1] = __float_as_uint(sm[AT_P + (r0 + 8) * 36 + kb + fc]);
            a[2] = __float_as_uint(sm[AT_P + r0 * 36 + kb + fc + 4]);
            a[3] = __float_as_uint(sm[AT_P + (r0 + 8) * 36 + kb + fc + 4]);
#pragma unroll
            for (int nf = 0; nf < 8; nf++) {
                uint32_t bb[2];
                bb[0] = __float_as_uint(Vs[(kb + fc) * 72 + nf * 8 + fr]);
                bb[1] = __float_as_uint(Vs[(kb + fc + 4) * 72 + nf * 8 + fr]);
                mma_tf32(acc_o[nf], a, bb);
            }
        }
    }

    float inv0 = 1.0f / l0, inv1 = 1.0f / l1;
    const size_t obase = (size_t)(b * SEQ) * DIM + h * DH;
#pragma unroll
    for (int nf = 0; nf < 8; nf++) {
        int col = nf * 8 + 2 * fc;
        float2 o0; o0.x = acc_o[nf][0] * inv0; o0.y = acc_o[nf][1] * inv0;
        float2 o1; o1.x = acc_o[nf][2] * inv1; o1.y = acc_o[nf][3] * inv1;
        *(float2*)&out[obase + (size_t)(q0 + r0) * DIM + col]     = o0;
        *(float2*)&out[obase + (size_t)(q0 + r0 + 8) * DIM + col] = o1;
    }
}

// ---------------- launch ----------------------------------------------------
extern "C" void kernel_launch(void* const* d_in, const int* in_sizes, int n_in,
                              void* d_out, int out_size)
{
    const float* x      = (const float*)d_in[0];
    const float* w_qkv  = (const float*)d_in[1];
    const float* b_qkv  = (const float*)d_in[2];
    const float* w_proj = (const float*)d_in[3];
    const float* b_proj = (const float*)d_in[4];
    const float* w_fc1  = (const float*)d_in[5];
    const float* b_fc1  = (const float*)d_in[6];
    const float* w_fc2  = (const float*)d_in[7];
    const float* b_fc2  = (const float*)d_in[8];
    const float* g1     = (const float*)d_in[9];
    const float* beta1  = (const float*)d_in[10];
    const float* g2     = (const float*)d_in[11];
    const float* beta2  = (const float*)d_in[12];
    float* out = (float*)d_out;

    float *p_ln, *p_qkv, *p_attn, *p_x1, *p_h;
    cudaGetSymbolAddress((void**)&p_ln,   g_ln);
    cudaGetSymbolAddress((void**)&p_qkv,  g_qkv);
    cudaGetSymbolAddress((void**)&p_attn, g_attn);
    cudaGetSymbolAddress((void**)&p_x1,   g_x1);
    cudaGetSymbolAddress((void**)&p_h,    g_h);

    cudaFuncSetAttribute(gemm_tc<0>, cudaFuncAttributeMaxDynamicSharedMemorySize, GEMM_SMEM);
    cudaFuncSetAttribute(gemm_tc<1>, cudaFuncAttributeMaxDynamicSharedMemorySize, GEMM_SMEM);
    cudaFuncSetAttribute(gemm_tc<2>, cudaFuncAttributeMaxDynamicSharedMemorySize, GEMM_SMEM);
    cudaFuncSetAttribute(attn_tc,    cudaFuncAttributeMaxDynamicSharedMemorySize, ATTN_SMEM);

    // 1) LN1
    ln_kernel<<<NTOK / 8, 256>>>(x, g1, beta1, p_ln);
    // 2) QKV GEMM: [8192,384] @ [384,1152] + bias
    gemm_tc<0><<<dim3(3 * DIM / 64, NTOK / 128), 256, GEMM_SMEM>>>(
        p_ln, w_qkv, b_qkv, nullptr, p_qkv, NTOK, DIM, 3 * DIM);
    // 3) tf32 flash attention (128 q-rows per CTA)
    attn_tc<<<dim3(SEQ / 128, BATCH * HEADS), 256, ATTN_SMEM>>>(p_qkv, p_attn);
    // 4) proj GEMM + bias + residual(x)
    gemm_tc<2><<<dim3(DIM / 64, NTOK / 128), 256, GEMM_SMEM>>>(
        p_attn, w_proj, b_proj, x, p_x1, NTOK, DIM, DIM);
    // 5) LN2
    ln_kernel<<<NTOK / 8, 256>>>(p_x1, g2, beta2, p_ln);
    // 6) FC1 GEMM + bias + exact GELU
    gemm_tc<1><<<dim3(HID / 64, NTOK / 128), 256, GEMM_SMEM>>>(
        p_ln, w_fc1, b_fc1, nullptr, p_h, NTOK, DIM, HID);
    // 7) FC2 GEMM + bias + residual(x1) -> d_out
    gemm_tc<2><<<dim3(DIM / 64, NTOK / 128), 256, GEMM_SMEM>>>(
        p_h, w_fc2, b_fc2, p_x1, out, NTOK, HID, DIM);
}

// round 16
// speedup vs baseline: 1.0894x; 1.0164x over previous
#include <cuda_runtime.h>
#include <math.h>
#include <stdint.h>

#define DIM   384
#define HID   1536
#define BATCH 4
#define SEQ   2048
#define NTOK  (BATCH*SEQ)   /* 8192 tokens */
#define HEADS 6
#define DH    64

// ---------------- scratch (device globals; no allocation allowed) ----------
__device__ float g_ln  [NTOK * DIM];
__device__ float g_qkv [NTOK * 3 * DIM];
__device__ float g_attn[NTOK * DIM];
__device__ float g_x1  [NTOK * DIM];
__device__ float g_h   [NTOK * HID];

// ---------------- helpers ---------------------------------------------------
__device__ __forceinline__ void mma_tf32(float c[4], const uint32_t a[4], const uint32_t b[2]) {
    asm volatile(
        "mma.sync.aligned.m16n8k8.row.col.f32.tf32.tf32.f32 "
        "{%0,%1,%2,%3}, {%4,%5,%6,%7}, {%8,%9}, {%0,%1,%2,%3};"
        : "+f"(c[0]), "+f"(c[1]), "+f"(c[2]), "+f"(c[3])
        : "r"(a[0]), "r"(a[1]), "r"(a[2]), "r"(a[3]), "r"(b[0]), "r"(b[1]));
}
__device__ __forceinline__ uint32_t cvta_s(const void* p) {
    return (uint32_t)__cvta_generic_to_shared(p);
}
__device__ __forceinline__ void cpa16(uint32_t dst, const void* src) {
    asm volatile("cp.async.cg.shared.global [%0], [%1], 16;" :: "r"(dst), "l"(src));
}
__device__ __forceinline__ void cp_commit() { asm volatile("cp.async.commit_group;"); }
__device__ __forceinline__ void cp_wait1()  { asm volatile("cp.async.wait_group 1;"); }
__device__ __forceinline__ void cp_wait0()  { asm volatile("cp.async.wait_group 0;"); }

// ---------------- LayerNorm: one warp per 384-elem row ---------------------
__global__ __launch_bounds__(256) void ln_kernel(
    const float* __restrict__ x, const float* __restrict__ g,
    const float* __restrict__ b, float* __restrict__ out)
{
    int warp = (blockIdx.x * blockDim.x + threadIdx.x) >> 5;
    int lane = threadIdx.x & 31;
    if (warp >= NTOK) return;
    const float* xr = x + (size_t)warp * DIM;

    float v[12];
    float s = 0.f;
#pragma unroll
    for (int i = 0; i < 12; i++) { v[i] = xr[lane + i * 32]; s += v[i]; }
#pragma unroll
    for (int o = 16; o > 0; o >>= 1) s += __shfl_xor_sync(0xffffffffu, s, o);
    float mu = s * (1.0f / DIM);
    float vs = 0.f;
#pragma unroll
    for (int i = 0; i < 12; i++) { float d = v[i] - mu; vs += d * d; }
#pragma unroll
    for (int o = 16; o > 0; o >>= 1) vs += __shfl_xor_sync(0xffffffffu, vs, o);
    float rstd = rsqrtf(vs * (1.0f / DIM) + 1e-6f);

    float* orow = out + (size_t)warp * DIM;
#pragma unroll
    for (int i = 0; i < 12; i++) {
        int c = lane + i * 32;
        orow[c] = (v[i] - mu) * rstd * g[c] + b[c];
    }
}

// ---------------- tf32 GEMM: 64x64 tile, 128 thr, 2-stage, 6 CTAs/SM --------
// A [M][K] row-major, W [K][N] row-major. Per stage: As[64][36] + Bs[32][72].
// 4 warps (2 wm x 2 wn), warp tile 32x32, m16n8k8 tf32 mma.
#define ASTG   (64 * 36)
#define BSTG   (32 * 72)
#define STGF   (ASTG + BSTG)
#define GEMM_SMEM (2 * STGF * 4)   /* 36864 bytes */

template <int EPI>
__global__ __launch_bounds__(128, 6) void gemm_tc(
    const float* __restrict__ A, const float* __restrict__ W,
    const float* __restrict__ bias, const float* __restrict__ res,
    float* __restrict__ C, int M, int K, int N)
{
    extern __shared__ float smem[];

    const int tid  = threadIdx.x;
    const int lane = tid & 31;
    const int wid  = tid >> 5;
    const int wm   = wid & 1;
    const int wn   = wid >> 1;
    const int bm   = blockIdx.y * 64;
    const int bn   = blockIdx.x * 64;

    const int a_kq = (tid & 7) << 2;     // A fill: k-quad
    const int a_mr = tid >> 3;           // A fill: row (x4 -> 64)
    const int b_cq = (tid & 15) << 2;    // B fill: n-quad
    const int b_kr = tid >> 4;           // B fill: k-row (x4 -> 32)
    const int fr   = lane >> 2;
    const int fc   = lane & 3;

    float acc[2][4][4];
#pragma unroll
    for (int mf = 0; mf < 2; mf++)
#pragma unroll
        for (int nf = 0; nf < 4; nf++)
#pragma unroll
            for (int i = 0; i < 4; i++) acc[mf][nf][i] = 0.f;

    const int NK = K >> 5;

    auto issue = [&](int kb) {
        float* dst = smem + (kb & 1) * STGF;
        const int k0 = kb << 5;
#pragma unroll
        for (int mi = 0; mi < 4; mi++) {
            int m = mi * 16 + a_mr;
            cpa16(cvta_s(dst + m * 36 + a_kq), &A[(size_t)(bm + m) * K + k0 + a_kq]);
        }
#pragma unroll
        for (int ki = 0; ki < 4; ki++) {
            int kk = ki * 8 + b_kr;
            cpa16(cvta_s(dst + ASTG + kk * 72 + b_cq),
                  &W[(size_t)(k0 + kk) * N + bn + b_cq]);
        }
        cp_commit();
    };

    issue(0);

    for (int kb = 0; kb < NK; kb++) {
        if (kb + 1 < NK) { issue(kb + 1); cp_wait1(); }
        else             { cp_wait0(); }
        __syncthreads();

        const float* As = smem + (kb & 1) * STGF;
        const float* Bs = As + ASTG;

#pragma unroll
        for (int ks = 0; ks < 4; ks++) {
            const int kb8 = ks * 8;
            uint32_t afr[2][4], bfr[4][2];
#pragma unroll
            for (int mf = 0; mf < 2; mf++) {
                int r = wm * 32 + mf * 16 + fr;
                int c = kb8 + fc;
                afr[mf][0] = __float_as_uint(As[r * 36 + c]);
                afr[mf][1] = __float_as_uint(As[(r + 8) * 36 + c]);
                afr[mf][2] = __float_as_uint(As[r * 36 + c + 4]);
                afr[mf][3] = __float_as_uint(As[(r + 8) * 36 + c + 4]);
            }
#pragma unroll
            for (int nf = 0; nf < 4; nf++) {
                int n = wn * 32 + nf * 8 + fr;
                bfr[nf][0] = __float_as_uint(Bs[(kb8 + fc) * 72 + n]);
                bfr[nf][1] = __float_as_uint(Bs[(kb8 + fc + 4) * 72 + n]);
            }
#pragma unroll
            for (int mf = 0; mf < 2; mf++)
#pragma unroll
                for (int nf = 0; nf < 4; nf++)
                    mma_tf32(acc[mf][nf], afr[mf], bfr[nf]);
        }
        __syncthreads();   // protects buf^1 before next iteration's issue
    }

#pragma unroll
    for (int mf = 0; mf < 2; mf++) {
#pragma unroll
        for (int half = 0; half < 2; half++) {
            int row = bm + wm * 32 + mf * 16 + fr + half * 8;
#pragma unroll
            for (int nf = 0; nf < 4; nf++) {
                int col = bn + wn * 32 + nf * 8 + 2 * fc;
                float v0 = acc[mf][nf][half * 2 + 0] + bias[col];
                float v1 = acc[mf][nf][half * 2 + 1] + bias[col + 1];
                if (EPI == 1) {
                    v0 = 0.5f * v0 * (1.0f + erff(v0 * 0.70710678118654752f));
                    v1 = 0.5f * v1 * (1.0f + erff(v1 * 0.70710678118654752f));
                }
                if (EPI == 2) {
                    float2 r2 = *(const float2*)&res[(size_t)row * N + col];
                    v0 += r2.x; v1 += r2.y;
                }
                float2 o; o.x = v0; o.y = v1;
                *(float2*)&C[(size_t)row * N + col] = o;
            }
        }
    }
}

// ---------------- tf32 flash attention: 128 q-rows, 256 thr, dbuf K/V -------
// dyn smem floats: Q[128*68] | K[2][32*68] | V[2][32*72] | P[128*36]
#define AT_Q 0
#define AT_K 8704
#define AT_V 13056
#define AT_P 17664
#define ATTN_SMEM (22272 * 4)   /* 89088 bytes */

__global__ __launch_bounds__(256, 2) void attn_tc(
    const float* __restrict__ qkv, float* __restrict__ out)
{
    extern __shared__ float sm[];

    const int bh = blockIdx.y;
    const int b = bh / HEADS, h = bh % HEADS;
    const int q0 = blockIdx.x * 128;
    const int tid = threadIdx.x;
    const int lane = tid & 31;
    const int wid = tid >> 5;
    const int fr = lane >> 2, fc = lane & 3;
    const int r0 = wid * 16 + fr;
    const size_t rstride = 3 * DIM;
    const size_t base = (size_t)b * SEQ * rstride + h * DH;

#pragma unroll
    for (int t = 0; t < 8; t++) {
        int q = tid + t * 256;
        int r = q >> 4, dq = (q & 15) * 4;
        float4 v = *(const float4*)&qkv[base + (size_t)(q0 + r) * rstride + dq];
        v.x *= 0.125f; v.y *= 0.125f; v.z *= 0.125f; v.w *= 0.125f;
        *(float4*)&sm[AT_Q + r * 68 + dq] = v;
    }

    auto issue_kv = [&](int kt, int buf) {
#pragma unroll
        for (int t = 0; t < 2; t++) {
            int q = tid + t * 256;
            int r = q >> 4, dq = (q & 15) * 4;
            cpa16(cvta_s(&sm[AT_K + buf * 2176 + r * 68 + dq]),
                  &qkv[base + DIM + (size_t)(kt + r) * rstride + dq]);
            cpa16(cvta_s(&sm[AT_V + buf * 2304 + r * 72 + dq]),
                  &qkv[base + 2 * DIM + (size_t)(kt + r) * rstride + dq]);
        }
        cp_commit();
    };

    issue_kv(0, 0);

    float m0 = -1e30f, m1 = -1e30f, l0 = 0.f, l1 = 0.f;
    float acc_o[8][4];
#pragma unroll
    for (int nf = 0; nf < 8; nf++)
#pragma unroll
        for (int i = 0; i < 4; i++) acc_o[nf][i] = 0.f;

    const int NT = SEQ / 32;
    for (int it = 0; it < NT; it++) {
        const int buf = it & 1;
        __syncthreads();
        if (it + 1 < NT) { issue_kv((it + 1) * 32, buf ^ 1); cp_wait1(); }
        else             { cp_wait0(); }
        __syncthreads();

        const float* Ks = &sm[AT_K + buf * 2176];
        const float* Vs = &sm[AT_V + buf * 2304];

        float s[4][4];
#pragma unroll
        for (int nf = 0; nf < 4; nf++)
#pragma unroll
            for (int i = 0; i < 4; i++) s[nf][i] = 0.f;
#pragma unroll
        for (int ks = 0; ks < 8; ks++) {
            const int kb = ks * 8;
            uint32_t a[4];
            a[0] = __float_as_uint(sm[AT_Q + r0 * 68 + kb + fc]);
            a[1] = __float_as_uint(sm[AT_Q + (r0 + 8) * 68 + kb + fc]);
            a[2] = __float_as_uint(sm[AT_Q + r0 * 68 + kb + fc + 4]);
            a[3] = __float_as_uint(sm[AT_Q + (r0 + 8) * 68 + kb + fc + 4]);
#pragma unroll
            for (int nf = 0; nf < 4; nf++) {
                uint32_t bb[2];
                bb[0] = __float_as_uint(Ks[(nf * 8 + fr) * 68 + kb + fc]);
                bb[1] = __float_as_uint(Ks[(nf * 8 + fr) * 68 + kb + fc + 4]);
                mma_tf32(s[nf], a, bb);
            }
        }

        float mx0 = -1e30f, mx1 = -1e30f;
#pragma unroll
        for (int nf = 0; nf < 4; nf++) {
            mx0 = fmaxf(mx0, fmaxf(s[nf][0], s[nf][1]));
            mx1 = fmaxf(mx1, fmaxf(s[nf][2], s[nf][3]));
        }
        mx0 = fmaxf(mx0, __shfl_xor_sync(0xffffffffu, mx0, 1));
        mx0 = fmaxf(mx0, __shfl_xor_sync(0xffffffffu, mx0, 2));
        mx1 = fmaxf(mx1, __shfl_xor_sync(0xffffffffu, mx1, 1));
        mx1 = fmaxf(mx1, __shfl_xor_sync(0xffffffffu, mx1, 2));
        float mn0 = fmaxf(m0, mx0), mn1 = fmaxf(m1, mx1);
        float al0 = __expf(m0 - mn0), al1 = __expf(m1 - mn1);
        float sum0 = 0.f, sum1 = 0.f;
#pragma unroll
        for (int nf = 0; nf < 4; nf++) {
            s[nf][0] = __expf(s[nf][0] - mn0);
            s[nf][1] = __expf(s[nf][1] - mn0);
            s[nf][2] = __expf(s[nf][2] - mn1);
            s[nf][3] = __expf(s[nf][3] - mn1);
            sum0 += s[nf][0] + s[nf][1];
            sum1 += s[nf][2] + s[nf][3];
        }
        sum0 += __shfl_xor_sync(0xffffffffu, sum0, 1);
        sum0 += __shfl_xor_sync(0xffffffffu, sum0, 2);
        sum1 += __shfl_xor_sync(0xffffffffu, sum1, 1);
        sum1 += __shfl_xor_sync(0xffffffffu, sum1, 2);
        l0 = l0 * al0 + sum0; l1 = l1 * al1 + sum1;
        m0 = mn0; m1 = mn1;
#pragma unroll
        for (int nf = 0; nf < 8; nf++) {
            acc_o[nf][0] *= al0; acc_o[nf][1] *= al0;
            acc_o[nf][2] *= al1; acc_o[nf][3] *= al1;
        }

#pragma unroll
        for (int nf = 0; nf < 4; nf++) {
            float2 p01; p01.x = s[nf][0]; p01.y = s[nf][1];
            float2 p23; p23.x = s[nf][2]; p23.y = s[nf][3];
            *(float2*)&sm[AT_P + r0 * 36 + nf * 8 + 2 * fc]       = p01;
            *(float2*)&sm[AT_P + (r0 + 8) * 36 + nf * 8 + 2 * fc] = p23;
        }
        __syncwarp();

#pragma unroll
        for (int ks = 0; ks < 4; ks++) {
            const int kb = ks * 8;
            uint32_t a[4];
            a[0] = __float_as_uint(sm[AT_P + r0 * 36 + kb + fc]);
            a[1] = __float_as_uint(sm[AT_P + (r0 + 8) * 36 + kb + fc]);
            a[2] = __float_as_uint(sm[AT_P + r0 * 36 + kb + fc + 4]);
            a[3] = __float_as_uint(sm[AT_P + (r0 + 8) * 36 + kb + fc + 4]);
#pragma unroll
            for (int nf = 0; nf < 8; nf++) {
                uint32_t bb[2];
                bb[0] = __float_as_uint(Vs[(kb + fc) * 72 + nf * 8 + fr]);
                bb[1] = __float_as_uint(Vs[(kb + fc + 4) * 72 + nf * 8 + fr]);
                mma_tf32(acc_o[nf], a, bb);
            }
        }
    }

    float inv0 = 1.0f / l0, inv1 = 1.0f / l1;
    const size_t obase = (size_t)(b * SEQ) * DIM + h * DH;
#pragma unroll
    for (int nf = 0; nf < 8; nf++) {
        int col = nf * 8 + 2 * fc;
        float2 o0; o0.x = acc_o[nf][0] * inv0; o0.y = acc_o[nf][1] * inv0;
        float2 o1; o1.x = acc_o[nf][2] * inv1; o1.y = acc_o[nf][3] * inv1;
        *(float2*)&out[obase + (size_t)(q0 + r0) * DIM + col]     = o0;
        *(float2*)&out[obase + (size_t)(q0 + r0 + 8) * DIM + col] = o1;
    }
}

// ---------------- launch ----------------------------------------------------
extern "C" void kernel_launch(void* const* d_in, const int* in_sizes, int n_in,
                              void* d_out, int out_size)
{
    const float* x      = (const float*)d_in[0];
    const float* w_qkv  = (const float*)d_in[1];
    const float* b_qkv  = (const float*)d_in[2];
    const float* w_proj = (const float*)d_in[3];
    const float* b_proj = (const float*)d_in[4];
    const float* w_fc1  = (const float*)d_in[5];
    const float* b_fc1  = (const float*)d_in[6];
    const float* w_fc2  = (const float*)d_in[7];
    const float* b_fc2  = (const float*)d_in[8];
    const float* g1     = (const float*)d_in[9];
    const float* beta1  = (const float*)d_in[10];
    const float* g2     = (const float*)d_in[11];
    const float* beta2  = (const float*)d_in[12];
    float* out = (float*)d_out;

    float *p_ln, *p_qkv, *p_attn, *p_x1, *p_h;
    cudaGetSymbolAddress((void**)&p_ln,   g_ln);
    cudaGetSymbolAddress((void**)&p_qkv,  g_qkv);
    cudaGetSymbolAddress((void**)&p_attn, g_attn);
    cudaGetSymbolAddress((void**)&p_x1,   g_x1);
    cudaGetSymbolAddress((void**)&p_h,    g_h);

    cudaFuncSetAttribute(gemm_tc<0>, cudaFuncAttributeMaxDynamicSharedMemorySize, GEMM_SMEM);
    cudaFuncSetAttribute(gemm_tc<1>, cudaFuncAttributeMaxDynamicSharedMemorySize, GEMM_SMEM);
    cudaFuncSetAttribute(gemm_tc<2>, cudaFuncAttributeMaxDynamicSharedMemorySize, GEMM_SMEM);
    cudaFuncSetAttribute(attn_tc,    cudaFuncAttributeMaxDynamicSharedMemorySize, ATTN_SMEM);

    // 1) LN1
    ln_kernel<<<NTOK / 8, 256>>>(x, g1, beta1, p_ln);
    // 2) QKV GEMM: [8192,384] @ [384,1152] + bias
    gemm_tc<0><<<dim3(3 * DIM / 64, NTOK / 64), 128, GEMM_SMEM>>>(
        p_ln, w_qkv, b_qkv, nullptr, p_qkv, NTOK, DIM, 3 * DIM);
    // 3) tf32 flash attention (128 q-rows per CTA)
    attn_tc<<<dim3(SEQ / 128, BATCH * HEADS), 256, ATTN_SMEM>>>(p_qkv, p_attn);
    // 4) proj GEMM + bias + residual(x)
    gemm_tc<2><<<dim3(DIM / 64, NTOK / 64), 128, GEMM_SMEM>>>(
        p_attn, w_proj, b_proj, x, p_x1, NTOK, DIM, DIM);
    // 5) LN2
    ln_kernel<<<NTOK / 8, 256>>>(p_x1, g2, beta2, p_ln);
    // 6) FC1 GEMM + bias + exact GELU
    gemm_tc<1><<<dim3(HID / 64, NTOK / 64), 128, GEMM_SMEM>>>(
        p_ln, w_fc1, b_fc1, nullptr, p_h, NTOK, DIM, HID);
    // 7) FC2 GEMM + bias + residual(x1) -> d_out
    gemm_tc<2><<<dim3(DIM / 64, NTOK / 64), 128, GEMM_SMEM>>>(
        p_h, w_fc2, b_fc2, p_x1, out, NTOK, HID, DIM);
}

// round 17
// speedup vs baseline: 1.1087x; 1.0177x over previous
#include <cuda_runtime.h>
#include <math.h>
#include <stdint.h>

#define DIM   384
#define HID   1536
#define BATCH 4
#define SEQ   2048
#define NTOK  (BATCH*SEQ)   /* 8192 tokens */
#define HEADS 6
#define DH    64

// ---------------- scratch (device globals; no allocation allowed) ----------
__device__ float g_ln  [NTOK * DIM];
__device__ float g_qkv [NTOK * 3 * DIM];
__device__ float g_attn[NTOK * DIM];
__device__ float g_x1  [NTOK * DIM];
__device__ float g_h   [NTOK * HID];

// ---------------- helpers ---------------------------------------------------
__device__ __forceinline__ void mma_tf32(float c[4], const uint32_t a[4], const uint32_t b[2]) {
    asm volatile(
        "mma.sync.aligned.m16n8k8.row.col.f32.tf32.tf32.f32 "
        "{%0,%1,%2,%3}, {%4,%5,%6,%7}, {%8,%9}, {%0,%1,%2,%3};"
        : "+f"(c[0]), "+f"(c[1]), "+f"(c[2]), "+f"(c[3])
        : "r"(a[0]), "r"(a[1]), "r"(a[2]), "r"(a[3]), "r"(b[0]), "r"(b[1]));
}
__device__ __forceinline__ uint32_t cvta_s(const void* p) {
    return (uint32_t)__cvta_generic_to_shared(p);
}
__device__ __forceinline__ void cpa16(uint32_t dst, const void* src) {
    asm volatile("cp.async.cg.shared.global [%0], [%1], 16;" :: "r"(dst), "l"(src));
}
__device__ __forceinline__ void cp_commit() { asm volatile("cp.async.commit_group;"); }
__device__ __forceinline__ void cp_wait1()  { asm volatile("cp.async.wait_group 1;"); }
__device__ __forceinline__ void cp_wait0()  { asm volatile("cp.async.wait_group 0;"); }

// ---------------- LayerNorm: one warp per 384-elem row ---------------------
__global__ __launch_bounds__(256) void ln_kernel(
    const float* __restrict__ x, const float* __restrict__ g,
    const float* __restrict__ b, float* __restrict__ out)
{
    int warp = (blockIdx.x * blockDim.x + threadIdx.x) >> 5;
    int lane = threadIdx.x & 31;
    if (warp >= NTOK) return;
    const float* xr = x + (size_t)warp * DIM;

    float v[12];
    float s = 0.f;
#pragma unroll
    for (int i = 0; i < 12; i++) { v[i] = xr[lane + i * 32]; s += v[i]; }
#pragma unroll
    for (int o = 16; o > 0; o >>= 1) s += __shfl_xor_sync(0xffffffffu, s, o);
    float mu = s * (1.0f / DIM);
    float vs = 0.f;
#pragma unroll
    for (int i = 0; i < 12; i++) { float d = v[i] - mu; vs += d * d; }
#pragma unroll
    for (int o = 16; o > 0; o >>= 1) vs += __shfl_xor_sync(0xffffffffu, vs, o);
    float rstd = rsqrtf(vs * (1.0f / DIM) + 1e-6f);

    float* orow = out + (size_t)warp * DIM;
#pragma unroll
    for (int i = 0; i < 12; i++) {
        int c = lane + i * 32;
        orow[c] = (v[i] - mu) * rstd * g[c] + b[c];
    }
}

// ---------------- tf32 GEMM: 128x64 CTA tile, 128 thr, warp tile 64x32 ------
// A [M][K] row-major, W [K][N] row-major. Per stage: As[128][36] + Bs[32][72].
// 4 warps (2 wm x 2 wn), warp tile 64x32 -> 25% less smem read / 33% less
// write traffic per FLOP vs 32x32 warp tile. 2-stage cp.async, 4 CTAs/SM.
#define ASTG   (128 * 36)
#define BSTG   (32 * 72)
#define STGF   (ASTG + BSTG)
#define GEMM_SMEM (2 * STGF * 4)   /* 55296 bytes */

template <int EPI>
__global__ __launch_bounds__(128, 4) void gemm_tc(
    const float* __restrict__ A, const float* __restrict__ W,
    const float* __restrict__ bias, const float* __restrict__ res,
    float* __restrict__ C, int M, int K, int N)
{
    extern __shared__ float smem[];

    const int tid  = threadIdx.x;
    const int lane = tid & 31;
    const int wid  = tid >> 5;
    const int wm   = wid & 1;          // 0..1 (m-warps, 64 rows each)
    const int wn   = wid >> 1;         // 0..1 (n-warps, 32 cols each)
    const int bm   = blockIdx.y * 128;
    const int bn   = blockIdx.x * 64;

    const int a_kq = (tid & 7) << 2;   // A fill: k-quad
    const int a_mr = tid >> 3;         // A fill: row 0..15 (x8 -> 128)
    const int b_cq = (tid & 15) << 2;  // B fill: n-quad
    const int b_kr = tid >> 4;         // B fill: k-row 0..7 (x4 -> 32)
    const int fr   = lane >> 2;
    const int fc   = lane & 3;

    float acc[4][4][4];
#pragma unroll
    for (int mf = 0; mf < 4; mf++)
#pragma unroll
        for (int nf = 0; nf < 4; nf++)
#pragma unroll
            for (int i = 0; i < 4; i++) acc[mf][nf][i] = 0.f;

    const int NK = K >> 5;

    auto issue = [&](int kb) {
        float* dst = smem + (kb & 1) * STGF;
        const int k0 = kb << 5;
#pragma unroll
        for (int mi = 0; mi < 8; mi++) {
            int m = mi * 16 + a_mr;
            cpa16(cvta_s(dst + m * 36 + a_kq), &A[(size_t)(bm + m) * K + k0 + a_kq]);
        }
#pragma unroll
        for (int ki = 0; ki < 4; ki++) {
            int kk = ki * 8 + b_kr;
            cpa16(cvta_s(dst + ASTG + kk * 72 + b_cq),
                  &W[(size_t)(k0 + kk) * N + bn + b_cq]);
        }
        cp_commit();
    };

    issue(0);

    for (int kb = 0; kb < NK; kb++) {
        if (kb + 1 < NK) { issue(kb + 1); cp_wait1(); }
        else             { cp_wait0(); }
        __syncthreads();

        const float* As = smem + (kb & 1) * STGF;
        const float* Bs = As + ASTG;

#pragma unroll
        for (int ks = 0; ks < 4; ks++) {
            const int kb8 = ks * 8;
            uint32_t afr[4][4], bfr[4][2];
#pragma unroll
            for (int mf = 0; mf < 4; mf++) {
                int r = wm * 64 + mf * 16 + fr;
                int c = kb8 + fc;
                afr[mf][0] = __float_as_uint(As[r * 36 + c]);
                afr[mf][1] = __float_as_uint(As[(r + 8) * 36 + c]);
                afr[mf][2] = __float_as_uint(As[r * 36 + c + 4]);
                afr[mf][3] = __float_as_uint(As[(r + 8) * 36 + c + 4]);
            }
#pragma unroll
            for (int nf = 0; nf < 4; nf++) {
                int n = wn * 32 + nf * 8 + fr;
                bfr[nf][0] = __float_as_uint(Bs[(kb8 + fc) * 72 + n]);
                bfr[nf][1] = __float_as_uint(Bs[(kb8 + fc + 4) * 72 + n]);
            }
#pragma unroll
            for (int mf = 0; mf < 4; mf++)
#pragma unroll
                for (int nf = 0; nf < 4; nf++)
                    mma_tf32(acc[mf][nf], afr[mf], bfr[nf]);
        }
        __syncthreads();   // protects buf^1 before next iteration's issue
    }

#pragma unroll
    for (int mf = 0; mf < 4; mf++) {
#pragma unroll
        for (int half = 0; half < 2; half++) {
            int row = bm + wm * 64 + mf * 16 + fr + half * 8;
#pragma unroll
            for (int nf = 0; nf < 4; nf++) {
                int col = bn + wn * 32 + nf * 8 + 2 * fc;
                float v0 = acc[mf][nf][half * 2 + 0] + bias[col];
                float v1 = acc[mf][nf][half * 2 + 1] + bias[col + 1];
                if (EPI == 1) {
                    v0 = 0.5f * v0 * (1.0f + erff(v0 * 0.70710678118654752f));
                    v1 = 0.5f * v1 * (1.0f + erff(v1 * 0.70710678118654752f));
                }
                if (EPI == 2) {
                    float2 r2 = *(const float2*)&res[(size_t)row * N + col];
                    v0 += r2.x; v1 += r2.y;
                }
                float2 o; o.x = v0; o.y = v1;
                *(float2*)&C[(size_t)row * N + col] = o;
            }
        }
    }
}

// ---------------- tf32 flash attention: 128 q-rows, 256 thr, dbuf K/V -------
// dyn smem floats: Q[128*68] | K[2][32*68] | V[2][32*72] | P[128*36]
#define AT_Q 0
#define AT_K 8704
#define AT_V 13056
#define AT_P 17664
#define ATTN_SMEM (22272 * 4)   /* 89088 bytes */

__global__ __launch_bounds__(256, 2) void attn_tc(
    const float* __restrict__ qkv, float* __restrict__ out)
{
    extern __shared__ float sm[];

    const int bh = blockIdx.y;
    const int b = bh / HEADS, h = bh % HEADS;
    const int q0 = blockIdx.x * 128;
    const int tid = threadIdx.x;
    const int lane = tid & 31;
    const int wid = tid >> 5;
    const int fr = lane >> 2, fc = lane & 3;
    const int r0 = wid * 16 + fr;
    const size_t rstride = 3 * DIM;
    const size_t base = (size_t)b * SEQ * rstride + h * DH;

#pragma unroll
    for (int t = 0; t < 8; t++) {
        int q = tid + t * 256;
        int r = q >> 4, dq = (q & 15) * 4;
        float4 v = *(const float4*)&qkv[base + (size_t)(q0 + r) * rstride + dq];
        v.x *= 0.125f; v.y *= 0.125f; v.z *= 0.125f; v.w *= 0.125f;
        *(float4*)&sm[AT_Q + r * 68 + dq] = v;
    }

    auto issue_kv = [&](int kt, int buf) {
#pragma unroll
        for (int t = 0; t < 2; t++) {
            int q = tid + t * 256;
            int r = q >> 4, dq = (q & 15) * 4;
            cpa16(cvta_s(&sm[AT_K + buf * 2176 + r * 68 + dq]),
                  &qkv[base + DIM + (size_t)(kt + r) * rstride + dq]);
            cpa16(cvta_s(&sm[AT_V + buf * 2304 + r * 72 + dq]),
                  &qkv[base + 2 * DIM + (size_t)(kt + r) * rstride + dq]);
        }
        cp_commit();
    };

    issue_kv(0, 0);

    float m0 = -1e30f, m1 = -1e30f, l0 = 0.f, l1 = 0.f;
    float acc_o[8][4];
#pragma unroll
    for (int nf = 0; nf < 8; nf++)
#pragma unroll
        for (int i = 0; i < 4; i++) acc_o[nf][i] = 0.f;

    const int NT = SEQ / 32;
    for (int it = 0; it < NT; it++) {
        const int buf = it & 1;
        __syncthreads();
        if (it + 1 < NT) { issue_kv((it + 1) * 32, buf ^ 1); cp_wait1(); }
        else             { cp_wait0(); }
        __syncthreads();

        const float* Ks = &sm[AT_K + buf * 2176];
        const float* Vs = &sm[AT_V + buf * 2304];

        float s[4][4];
#pragma unroll
        for (int nf = 0; nf < 4; nf++)
#pragma unroll
            for (int i = 0; i < 4; i++) s[nf][i] = 0.f;
#pragma unroll
        for (int ks = 0; ks < 8; ks++) {
            const int kb = ks * 8;
            uint32_t a[4];
            a[0] = __float_as_uint(sm[AT_Q + r0 * 68 + kb + fc]);
            a[1] = __float_as_uint(sm[AT_Q + (r0 + 8) * 68 + kb + fc]);
            a[2] = __float_as_uint(sm[AT_Q + r0 * 68 + kb + fc + 4]);
            a[3] = __float_as_uint(sm[AT_Q + (r0 + 8) * 68 + kb + fc + 4]);
#pragma unroll
            for (int nf = 0; nf < 4; nf++) {
                uint32_t bb[2];
                bb[0] = __float_as_uint(Ks[(nf * 8 + fr) * 68 + kb + fc]);
                bb[1] = __float_as_uint(Ks[(nf * 8 + fr) * 68 + kb + fc + 4]);
                mma_tf32(s[nf], a, bb);
            }
        }

        float mx0 = -1e30f, mx1 = -1e30f;
#pragma unroll
        for (int nf = 0; nf < 4; nf++) {
            mx0 = fmaxf(mx0, fmaxf(s[nf][0], s[nf][1]));
            mx1 = fmaxf(mx1, fmaxf(s[nf][2], s[nf][3]));
        }
        mx0 = fmaxf(mx0, __shfl_xor_sync(0xffffffffu, mx0, 1));
        mx0 = fmaxf(mx0, __shfl_xor_sync(0xffffffffu, mx0, 2));
        mx1 = fmaxf(mx1, __shfl_xor_sync(0xffffffffu, mx1, 1));
        mx1 = fmaxf(mx1, __shfl_xor_sync(0xffffffffu, mx1, 2));
        float mn0 = fmaxf(m0, mx0), mn1 = fmaxf(m1, mx1);
        float al0 = __expf(m0 - mn0), al1 = __expf(m1 - mn1);
        float sum0 = 0.f, sum1 = 0.f;
#pragma unroll
        for (int nf = 0; nf < 4; nf++) {
            s[nf][0] = __expf(s[nf][0] - mn0);
            s[nf][1] = __expf(s[nf][1] - mn0);
            s[nf][2] = __expf(s[nf][2] - mn1);
            s[nf][3] = __expf(s[nf][3] - mn1);
            sum0 += s[nf][0] + s[nf][1];
            sum1 += s[nf][2] + s[nf][3];
        }
        sum0 += __shfl_xor_sync(0xffffffffu, sum0, 1);
        sum0 += __shfl_xor_sync(0xffffffffu, sum0, 2);
        sum1 += __shfl_xor_sync(0xffffffffu, sum1, 1);
        sum1 += __shfl_xor_sync(0xffffffffu, sum1, 2);
        l0 = l0 * al0 + sum0; l1 = l1 * al1 + sum1;
        m0 = mn0; m1 = mn1;
#pragma unroll
        for (int nf = 0; nf < 8; nf++) {
            acc_o[nf][0] *= al0; acc_o[nf][1] *= al0;
            acc_o[nf][2] *= al1; acc_o[nf][3] *= al1;
        }

#pragma unroll
        for (int nf = 0; nf < 4; nf++) {
            float2 p01; p01.x = s[nf][0]; p01.y = s[nf][1];
            float2 p23; p23.x = s[nf][2]; p23.y = s[nf][3];
            *(float2*)&sm[AT_P + r0 * 36 + nf * 8 + 2 * fc]       = p01;
            *(float2*)&sm[AT_P + (r0 + 8) * 36 + nf * 8 + 2 * fc] = p23;
        }
        __syncwarp();

#pragma unroll
        for (int ks = 0; ks < 4; ks++) {
            const int kb = ks * 8;
            uint32_t a[4];
            a[0] = __float_as_uint(sm[AT_P + r0 * 36 + kb + fc]);
            a[1] = __float_as_uint(sm[AT_P + (r0 + 8) * 36 + kb + fc]);
            a[2] = __float_as_uint(sm[AT_P + r0 * 36 + kb + fc + 4]);
            a[3] = __float_as_uint(sm[AT_P + (r0 + 8) * 36 + kb + fc + 4]);
#pragma unroll
            for (int nf = 0; nf < 8; nf++) {
                uint32_t bb[2];
                bb[0] = __float_as_uint(Vs[(kb + fc) * 72 + nf * 8 + fr]);
                bb[1] = __float_as_uint(Vs[(kb + fc + 4) * 72 + nf * 8 + fr]);
                mma_tf32(acc_o[nf], a, bb);
            }
        }
    }

    float inv0 = 1.0f / l0, inv1 = 1.0f / l1;
    const size_t obase = (size_t)(b * SEQ) * DIM + h * DH;
#pragma unroll
    for (int nf = 0; nf < 8; nf++) {
        int col = nf * 8 + 2 * fc;
        float2 o0; o0.x = acc_o[nf][0] * inv0; o0.y = acc_o[nf][1] * inv0;
        float2 o1; o1.x = acc_o[nf][2] * inv1; o1.y = acc_o[nf][3] * inv1;
        *(float2*)&out[obase + (size_t)(q0 + r0) * DIM + col]     = o0;
        *(float2*)&out[obase + (size_t)(q0 + r0 + 8) * DIM + col] = o1;
    }
}

// ---------------- launch ----------------------------------------------------
extern "C" void kernel_launch(void* const* d_in, const int* in_sizes, int n_in,
                              void* d_out, int out_size)
{
    const float* x      = (const float*)d_in[0];
    const float* w_qkv  = (const float*)d_in[1];
    const float* b_qkv  = (const float*)d_in[2];
    const float* w_proj = (const float*)d_in[3];
    const float* b_proj = (const float*)d_in[4];
    const float* w_fc1  = (const float*)d_in[5];
    const float* b_fc1  = (const float*)d_in[6];
    const float* w_fc2  = (const float*)d_in[7];
    const float* b_fc2  = (const float*)d_in[8];
    const float* g1     = (const float*)d_in[9];
    const float* beta1  = (const float*)d_in[10];
    const float* g2     = (const float*)d_in[11];
    const float* beta2  = (const float*)d_in[12];
    float* out = (float*)d_out;

    float *p_ln, *p_qkv, *p_attn, *p_x1, *p_h;
    cudaGetSymbolAddress((void**)&p_ln,   g_ln);
    cudaGetSymbolAddress((void**)&p_qkv,  g_qkv);
    cudaGetSymbolAddress((void**)&p_attn, g_attn);
    cudaGetSymbolAddress((void**)&p_x1,   g_x1);
    cudaGetSymbolAddress((void**)&p_h,    g_h);

    cudaFuncSetAttribute(gemm_tc<0>, cudaFuncAttributeMaxDynamicSharedMemorySize, GEMM_SMEM);
    cudaFuncSetAttribute(gemm_tc<1>, cudaFuncAttributeMaxDynamicSharedMemorySize, GEMM_SMEM);
    cudaFuncSetAttribute(gemm_tc<2>, cudaFuncAttributeMaxDynamicSharedMemorySize, GEMM_SMEM);
    cudaFuncSetAttribute(attn_tc,    cudaFuncAttributeMaxDynamicSharedMemorySize, ATTN_SMEM);

    // 1) LN1
    ln_kernel<<<NTOK / 8, 256>>>(x, g1, beta1, p_ln);
    // 2) QKV GEMM: [8192,384] @ [384,1152] + bias
    gemm_tc<0><<<dim3(3 * DIM / 64, NTOK / 128), 128, GEMM_SMEM>>>(
        p_ln, w_qkv, b_qkv, nullptr, p_qkv, NTOK, DIM, 3 * DIM);
    // 3) tf32 flash attention (128 q-rows per CTA)
    attn_tc<<<dim3(SEQ / 128, BATCH * HEADS), 256, ATTN_SMEM>>>(p_qkv, p_attn);
    // 4) proj GEMM + bias + residual(x)
    gemm_tc<2><<<dim3(DIM / 64, NTOK / 128), 128, GEMM_SMEM>>>(
        p_attn, w_proj, b_proj, x, p_x1, NTOK, DIM, DIM);
    // 5) LN2
    ln_kernel<<<NTOK / 8, 256>>>(p_x1, g2, beta2, p_ln);
    // 6) FC1 GEMM + bias + exact GELU
    gemm_tc<1><<<dim3(HID / 64, NTOK / 128), 128, GEMM_SMEM>>>(
        p_ln, w_fc1, b_fc1, nullptr, p_h, NTOK, DIM, HID);
    // 7) FC2 GEMM + bias + residual(x1) -> d_out
    gemm_tc<2><<<dim3(DIM / 64, NTOK / 128), 128, GEMM_SMEM>>>(
        p_h, w_fc2, b_fc2, p_x1, out, NTOK, HID, DIM);
}